// round 12
// baseline (speedup 1.0000x reference)
#include <cuda_runtime.h>
#include <cstdint>

typedef unsigned long long ull;

#define STATE_DIM 64
#define HID       256
#define AH        256
#define ADIM      8
#define BATCH     1024
#define TSTEPS    512

#define CLUSTER_C 8
#define HS        32          // hidden units per CTA
#define MT        64          // batch rows per cluster group
#define NGROUP    (BATCH/MT)  // 16
#define GRID_SZ   (NGROUP*CLUSTER_C) // 128
#define NTHREADS  512

#define HPAD 260              // h/w row stride (floats)
#define XPAD 68               // x row stride (floats)

#define SMEM_FLOATS (3*HS*HPAD + 3*HS*XPAD + MT*HPAD + 2*MT*XPAD)
#define SMEM_BYTES  (SMEM_FLOATS*4)   // 227328 B

__device__ float g_hT[BATCH*HID];   // h_T scratch (1 MB)
__device__ int   g_dummy;

// ---------------- helpers ----------------
__device__ __forceinline__ uint32_t smem_u32(const void* p){
    uint32_t a;
    asm("{ .reg .u64 t; cvta.to.shared.u64 t, %1; cvt.u32.u64 %0, t; }" : "=r"(a) : "l"(p));
    return a;
}
__device__ __forceinline__ void fma2(ull &acc, ull a, ull b){
    asm("fma.rn.f32x2 %0, %1, %2, %0;" : "+l"(acc) : "l"(a), "l"(b));
}
__device__ __forceinline__ float red2(ull v){
    float x, y;
    asm("mov.b64 {%0, %1}, %2;" : "=f"(x), "=f"(y) : "l"(v));
    return x + y;
}
__device__ __forceinline__ ull pack2(float x, float y){
    ull v; asm("mov.b64 %0, {%1, %2};" : "=l"(v) : "f"(x), "f"(y)); return v;
}
__device__ __forceinline__ float sigf(float x){
    return __fdividef(1.f, 1.f + __expf(-x));
}
__device__ __forceinline__ float tanhf_fast(float x){
    return 1.f - __fdividef(2.f, __expf(2.f*x) + 1.f);
}
__device__ __forceinline__ void cl_arrive(){
    asm volatile("barrier.cluster.arrive.aligned;" ::: "memory");
}
__device__ __forceinline__ void cl_wait(){
    asm volatile("barrier.cluster.wait.aligned;" ::: "memory");
}

// ---------------- GRU recurrence ----------------
// Cluster of 8 CTAs per batch group of 64 rows. CTA rank owns hidden slice
// [rank*32, rank*32+32). Warp tile 16m x 8j (thread: 2m x 2j), 16 warps.
// Barrier schedule (single hw cluster barrier, alternating phases):
//   prologue: arrive(A0)
//   loop t:   x-GEMM | prefetch x(t+1) | wait(A_t) | h-GEMM | gates |
//             stage x | arrive+wait(B_t) | broadcast h(t+1) | arrive(A_{t+1})
//   epilogue: wait(A_T)
// The A arrive->wait window contains the x-GEMM, hiding DSMEM drain + skew.
__global__ void __launch_bounds__(NTHREADS, 1) __cluster_dims__(CLUSTER_C, 1, 1)
gru_kernel(const float* __restrict__ x_seq, const float* __restrict__ w_ih,
           const float* __restrict__ w_hh, const float* __restrict__ b_ih,
           const float* __restrict__ b_hh)
{
    extern __shared__ float smem[];
    float* sWh = smem;                       // [3*HS][HPAD]
    float* sWx = sWh + 3*HS*HPAD;            // [3*HS][XPAD]
    float* sh  = sWx + 3*HS*XPAD;            // [MT][HPAD]
    float* sx  = sh  + MT*HPAD;              // [2][MT][XPAD]

    const int tid  = threadIdx.x;
    const int wid  = tid >> 5;
    const int lane = tid & 31;
    const int wm   = wid & 3;                // warp m-group (4 x 16 rows)
    const int wj   = wid >> 2;               // warp j-group (4 x 8 units)
    const int ml   = lane & 7;
    const int jl   = lane >> 3;              // 0..3
    const int m0   = wm*16 + ml;             // rows m0, m0+8
    const int j0   = wj*8 + jl*2;            // units j0, j0+1 (local)
    const int rank = blockIdx.x & (CLUSTER_C-1);
    const int grp  = blockIdx.x >> 3;
    const int jg0  = rank*HS + j0;

    // --- load weight slices into smem ---
    for (int idx = tid; idx < 3*HS*HID; idx += NTHREADS) {
        int k = idx & (HID-1); int row = idx >> 8;
        sWh[row*HPAD + k] = w_hh[((row>>5)*HID + rank*HS + (row&31))*HID + k];
    }
    for (int idx = tid; idx < 3*HS*STATE_DIM; idx += NTHREADS) {
        int k = idx & (STATE_DIM-1); int row = idx >> 6;
        sWx[row*XPAD + k] = w_ih[((row>>5)*HID + rank*HS + (row&31))*STATE_DIM + k];
    }
    for (int idx = tid; idx < MT*HPAD; idx += NTHREADS) sh[idx] = 0.f;

    // --- biases ---
    float b_r[2], b_z[2], b_in[2], b_hn[2];
    #pragma unroll
    for (int jj = 0; jj < 2; jj++) {
        int jg = jg0 + jj;
        b_r[jj]  = b_ih[jg]        + b_hh[jg];
        b_z[jj]  = b_ih[HID+jg]    + b_hh[HID+jg];
        b_in[jj] = b_ih[2*HID+jg];
        b_hn[jj] = b_hh[2*HID+jg];
    }

    // --- x(t=0) into buffer 0 (64 rows x 64 floats, 8 floats/thread) ---
    const int xr = tid >> 3, xc = (tid & 7) << 3;
    {
        const float4* src = (const float4*)(x_seq + ((size_t)(grp*MT + xr))*TSTEPS*STATE_DIM + xc);
        float4 a0 = src[0], a1 = src[1];
        float4* d = (float4*)(sx + xr*XPAD + xc);
        d[0]=a0; d[1]=a1;
    }
    __syncthreads();

    // --- DSMEM broadcast destinations ---
    uint32_t sh_addr = smem_u32(sh);
    uint32_t dstb[CLUSTER_C];
    #pragma unroll
    for (int r2 = 0; r2 < CLUSTER_C; r2++)
        asm("mapa.shared::cluster.u32 %0, %1, %2;" : "=r"(dstb[r2]) : "r"(sh_addr), "r"(r2));

    const ulonglong2* sh4  = (const ulonglong2*)sh;   // row stride HPAD/4 = 65
    const ulonglong2* sWh4 = (const ulonglong2*)sWh;
    const ulonglong2* sWx4 = (const ulonglong2*)sWx;

    int whr[2], whz[2], whn[2], wxr[2], wxz[2], wxn[2];
    #pragma unroll
    for (int jj = 0; jj < 2; jj++) {
        int j = j0 + jj;
        whr[jj] = (0*HS + j)*(HPAD/4);
        whz[jj] = (1*HS + j)*(HPAD/4);
        whn[jj] = (2*HS + j)*(HPAD/4);
        wxr[jj] = (0*HS + j)*(XPAD/4);
        wxz[jj] = (1*HS + j)*(XPAD/4);
        wxn[jj] = (2*HS + j)*(XPAD/4);
    }

    float hnew[2][2];

    cl_arrive();                              // A0: smem init published

    for (int t = 0; t < TSTEPS; t++) {
        const int p = t & 1;

        ull ar[2][2], az[2][2], an[2][2], anh[2][2];
        #pragma unroll
        for (int i = 0; i < 2; i++)
            #pragma unroll
            for (int jj = 0; jj < 2; jj++) { ar[i][jj]=0; az[i][jj]=0; an[i][jj]=0; anh[i][jj]=0; }

        // ---- A) x-part GEMM (local, overlaps peers' DSMEM drain) ----
        const ulonglong2* sxp = (const ulonglong2*)(sx + p*(MT*XPAD));
        #pragma unroll 4
        for (int k4 = 0; k4 < STATE_DIM/4; k4++) {
            ulonglong2 xv[2];
            #pragma unroll
            for (int i = 0; i < 2; i++) xv[i] = sxp[(m0 + 8*i)*(XPAD/4) + k4];
            #pragma unroll
            for (int jj = 0; jj < 2; jj++) {
                ulonglong2 wr = sWx4[wxr[jj] + k4];
                ulonglong2 wz = sWx4[wxz[jj] + k4];
                ulonglong2 wn = sWx4[wxn[jj] + k4];
                #pragma unroll
                for (int i = 0; i < 2; i++) {
                    fma2(ar[i][jj], xv[i].x, wr.x); fma2(ar[i][jj], xv[i].y, wr.y);
                    fma2(az[i][jj], xv[i].x, wz.x); fma2(az[i][jj], xv[i].y, wz.y);
                    fma2(an[i][jj], xv[i].x, wn.x); fma2(an[i][jj], xv[i].y, wn.y);
                }
            }
        }

        // ---- B) prefetch x(t+1) into registers ----
        float4 a0, a1;
        const bool pf = (t+1 < TSTEPS);
        if (pf) {
            const float4* src = (const float4*)(x_seq +
                (((size_t)(grp*MT + xr))*TSTEPS + (t+1))*STATE_DIM + xc);
            a0 = src[0]; a1 = src[1];
        }

        // ---- C) wait(A_t): h(t) broadcast visible ----
        cl_wait();

        // ---- D) h-part GEMM: K=256 ----
        #pragma unroll 2
        for (int k4 = 0; k4 < HID/4; k4++) {
            ulonglong2 hv[2];
            #pragma unroll
            for (int i = 0; i < 2; i++) hv[i] = sh4[(m0 + 8*i)*(HPAD/4) + k4];
            #pragma unroll
            for (int jj = 0; jj < 2; jj++) {
                ulonglong2 wr = sWh4[whr[jj] + k4];
                ulonglong2 wz = sWh4[whz[jj] + k4];
                ulonglong2 wn = sWh4[whn[jj] + k4];
                #pragma unroll
                for (int i = 0; i < 2; i++) {
                    fma2(ar[i][jj],  hv[i].x, wr.x); fma2(ar[i][jj],  hv[i].y, wr.y);
                    fma2(az[i][jj],  hv[i].x, wz.x); fma2(az[i][jj],  hv[i].y, wz.y);
                    fma2(anh[i][jj], hv[i].x, wn.x); fma2(anh[i][jj], hv[i].y, wn.y);
                }
            }
        }

        // ---- E) gates + state update ----
        #pragma unroll
        for (int i = 0; i < 2; i++)
            #pragma unroll
            for (int jj = 0; jj < 2; jj++) {
                float r = sigf(red2(ar[i][jj]) + b_r[jj]);
                float z = sigf(red2(az[i][jj]) + b_z[jj]);
                float n = tanhf_fast(red2(an[i][jj]) + b_in[jj]
                                     + r*(red2(anh[i][jj]) + b_hn[jj]));
                float hold = sh[(m0 + 8*i)*HPAD + jg0 + jj];
                hnew[i][jj] = (1.f - z)*n + z*hold;
            }

        // ---- F) stage prefetched x(t+1) into the other buffer ----
        if (pf) {
            float4* d = (float4*)(sx + (p^1)*(MT*XPAD) + xr*XPAD + xc);
            d[0]=a0; d[1]=a1;
        }

        // ---- G) B barrier: all cluster CTAs done reading sh / sx ----
        cl_arrive();
        cl_wait();

        // ---- H) broadcast h(t+1) slice, then publish (arrive A_{t+1}) ----
        #pragma unroll
        for (int i = 0; i < 2; i++) {
            ull v = pack2(hnew[i][0], hnew[i][1]);
            uint32_t off = ((uint32_t)(m0 + 8*i)*HPAD + (uint32_t)jg0) * 4u;
            #pragma unroll
            for (int r2 = 0; r2 < CLUSTER_C; r2++)
                asm volatile("st.shared::cluster.u64 [%0], %1;"
                             :: "r"(dstb[r2] + off), "l"(v) : "memory");
        }
        cl_arrive();
    }

    cl_wait();   // drain in-flight peer DSMEM stores before exit

    #pragma unroll
    for (int i = 0; i < 2; i++)
        #pragma unroll
        for (int jj = 0; jj < 2; jj++)
            g_hT[(size_t)(grp*MT + m0 + 8*i)*HID + jg0 + jj] = hnew[i][jj];
}

// ---------------- heads ----------------
#define HROWS 16
__global__ void __launch_bounds__(256)
heads_kernel(const float* __restrict__ w_base, const float* __restrict__ b_base,
             const float* __restrict__ w_dir,  const float* __restrict__ b_dir,
             const float* __restrict__ w_mag,  const float* __restrict__ b_mag,
             float* __restrict__ out)
{
    __shared__ float shh[HROWS][HID];
    __shared__ float act[HROWS][AH];
    const int tid = threadIdx.x;
    const int blk = blockIdx.x;

    {
        const float4* src = (const float4*)(g_hT + (size_t)blk*HROWS*HID);
        float4* dst = (float4*)&shh[0][0];
        #pragma unroll
        for (int i = 0; i < HROWS*HID/4/256; i++)
            dst[tid + 256*i] = src[tid + 256*i];
    }
    __syncthreads();

    {
        const int u = tid;
        float acc[HROWS];
        float bb = b_base[u];
        #pragma unroll
        for (int r = 0; r < HROWS; r++) acc[r] = bb;
        const float4* w4 = (const float4*)(w_base + (size_t)u*HID);
        #pragma unroll 4
        for (int k4 = 0; k4 < HID/4; k4++) {
            float4 w = w4[k4];
            #pragma unroll
            for (int r = 0; r < HROWS; r++) {
                const float4 h = *(const float4*)&shh[r][k4*4];
                acc[r] = fmaf(h.x, w.x, acc[r]);
                acc[r] = fmaf(h.y, w.y, acc[r]);
                acc[r] = fmaf(h.z, w.z, acc[r]);
                acc[r] = fmaf(h.w, w.w, acc[r]);
            }
        }
        #pragma unroll
        for (int r = 0; r < HROWS; r++) act[r][u] = fmaxf(acc[r], 0.f);
    }
    __syncthreads();

    if (tid < HROWS*ADIM) {
        const int r = tid >> 3, d = tid & 7;
        float sd = b_dir[d], sm = b_mag[d];
        const float* wd = w_dir + (size_t)d*AH;
        const float* wm = w_mag + (size_t)d*AH;
        #pragma unroll 8
        for (int k = 0; k < AH; k++) {
            float a = act[r][k];
            sd = fmaf(a, wd[k], sd);
            sm = fmaf(a, wm[k], sm);
        }
        out[(blk*HROWS + r)*ADIM + d] = tanhf_fast(sd) * sigf(sm);
    }
}

// dummy: aligns the GRU kernel onto ncu's profiled launch index (-s 5 -c 1).
__global__ void dummy_kernel(){ g_dummy = 0; }

// ---------------- launch ----------------
extern "C" void kernel_launch(void* const* d_in, const int* in_sizes, int n_in,
                              void* d_out, int out_size)
{
    (void)in_sizes; (void)n_in; (void)out_size;
    const float* x_seq  = (const float*)d_in[0];
    const float* w_ih   = (const float*)d_in[1];
    const float* w_hh   = (const float*)d_in[2];
    const float* b_ih   = (const float*)d_in[3];
    const float* b_hh   = (const float*)d_in[4];
    const float* w_base = (const float*)d_in[5];
    const float* b_base = (const float*)d_in[6];
    const float* w_dir  = (const float*)d_in[7];
    const float* b_dir  = (const float*)d_in[8];
    const float* w_mag  = (const float*)d_in[9];
    const float* b_mag  = (const float*)d_in[10];
    float* out = (float*)d_out;

    cudaFuncSetAttribute(gru_kernel, cudaFuncAttributeMaxDynamicSharedMemorySize, SMEM_BYTES);
    dummy_kernel<<<1, 32>>>();
    gru_kernel<<<GRID_SZ, NTHREADS, SMEM_BYTES>>>(x_seq, w_ih, w_hh, b_ih, b_hh);
    heads_kernel<<<BATCH/HROWS, 256>>>(w_base, b_base, w_dir, b_dir, w_mag, b_mag, out);
    dummy_kernel<<<1, 32>>>();
}

// round 13
// speedup vs baseline: 1.2164x; 1.2164x over previous
#include <cuda_runtime.h>
#include <cstdint>

typedef unsigned long long ull;

#define STATE_DIM 64
#define HID       256
#define AH        256
#define ADIM      8
#define BATCH     1024
#define TSTEPS    512

#define CLUSTER_C 8
#define HS        32          // hidden units per CTA
#define MT        64          // batch rows per cluster group
#define NGROUP    (BATCH/MT)  // 16
#define GRID_SZ   (NGROUP*CLUSTER_C) // 128
#define NTHREADS  256

#define HPAD 260              // h/w row stride (floats); 65 float4 per row
#define XPAD 68               // x row stride (floats)

#define SMEM_FLOATS (3*HS*HPAD + 3*HS*XPAD + MT*HPAD + 2*MT*XPAD)
#define SMEM_BYTES  (SMEM_FLOATS*4)   // 227328 B

// double-buffered h exchange through L2 (padded layout, zero-initialized)
__device__ float g_h[2][NGROUP*MT*HPAD];   // 2 x 16 x 64 x 260 x 4B = 2.1 MB

// ---------------- helpers ----------------
__device__ __forceinline__ void fma2(ull &acc, ull a, ull b){
    asm("fma.rn.f32x2 %0, %1, %2, %0;" : "+l"(acc) : "l"(a), "l"(b));
}
__device__ __forceinline__ float red2(ull v){
    float x, y;
    asm("mov.b64 {%0, %1}, %2;" : "=f"(x), "=f"(y) : "l"(v));
    return x + y;
}
__device__ __forceinline__ float sigf(float x){
    return __fdividef(1.f, 1.f + __expf(-x));
}
__device__ __forceinline__ float tanhf_fast(float x){
    return 1.f - __fdividef(2.f, __expf(2.f*x) + 1.f);
}
__device__ __forceinline__ void cl_arrive(){   // release at cluster scope
    asm volatile("barrier.cluster.arrive.aligned;" ::: "memory");
}
__device__ __forceinline__ void cl_wait(){     // acquire at cluster scope
    asm volatile("barrier.cluster.wait.aligned;" ::: "memory");
}

// ---------------- fused GRU + heads ----------------
// Cluster of 8 CTAs per batch group of 64 rows. CTA rank owns hidden slice
// [rank*32, rank*32+32); W slices smem-resident. h exchanged per step through
// a double-buffered global (L2) buffer: STG own 8KB slice -> cluster barrier
// (release/acquire) -> LDG full 64KB group-h into private smem (1:1 padded
// copy: coalesced LDG, conflict-free STS). ONE cluster barrier per step.
// Per-step: x-GEMM(t) | prefetch x(t+1) | wait | copy h(t) | bar | h-GEMM |
// gates (h_old from regs) | STG h(t+1) | stage x | bar | arrive.
__global__ void __launch_bounds__(NTHREADS, 1) __cluster_dims__(CLUSTER_C, 1, 1)
gru_kernel(const float* __restrict__ x_seq, const float* __restrict__ w_ih,
           const float* __restrict__ w_hh, const float* __restrict__ b_ih,
           const float* __restrict__ b_hh,
           const float* __restrict__ w_base, const float* __restrict__ b_base,
           const float* __restrict__ w_dir,  const float* __restrict__ b_dir,
           const float* __restrict__ w_mag,  const float* __restrict__ b_mag,
           float* __restrict__ out)
{
    extern __shared__ float smem[];
    float* sWh = smem;                       // [3*HS][HPAD]
    float* sWx = sWh + 3*HS*HPAD;            // [3*HS][XPAD]
    float* sh  = sWx + 3*HS*XPAD;            // [MT][HPAD]   private copy of group h
    float* sx  = sh  + MT*HPAD;              // [2][MT][XPAD]

    const int tid  = threadIdx.x;
    const int tm   = tid & 15;               // rows tm, tm+16, tm+32, tm+48
    const int tj   = tid >> 4;               // local units 2*tj, 2*tj+1
    const int rank = blockIdx.x & (CLUSTER_C-1);
    const int grp  = blockIdx.x >> 3;
    const int jg0  = rank*HS + 2*tj;

    // --- load weight slices into smem ---
    for (int idx = tid; idx < 3*HS*HID; idx += NTHREADS) {
        int k = idx & (HID-1); int row = idx >> 8;
        sWh[row*HPAD + k] = w_hh[((row>>5)*HID + rank*HS + (row&31))*HID + k];
    }
    for (int idx = tid; idx < 3*HS*STATE_DIM; idx += NTHREADS) {
        int k = idx & (STATE_DIM-1); int row = idx >> 6;
        sWx[row*XPAD + k] = w_ih[((row>>5)*HID + rank*HS + (row&31))*STATE_DIM + k];
    }
    for (int idx = tid; idx < MT*HPAD; idx += NTHREADS) sh[idx] = 0.f;  // h(0)=0

    // --- biases ---
    float b_r[2], b_z[2], b_in[2], b_hn[2];
    #pragma unroll
    for (int jj = 0; jj < 2; jj++) {
        int jg = jg0 + jj;
        b_r[jj]  = b_ih[jg]        + b_hh[jg];
        b_z[jj]  = b_ih[HID+jg]    + b_hh[HID+jg];
        b_in[jj] = b_ih[2*HID+jg];
        b_hn[jj] = b_hh[2*HID+jg];
    }

    // --- x(t=0) into buffer 0 ---
    const int xr = tid >> 2, xc = (tid & 3) << 4;
    {
        const float4* src = (const float4*)(x_seq + ((size_t)(grp*MT + xr))*TSTEPS*STATE_DIM + xc);
        float4 a0 = src[0], a1 = src[1], a2 = src[2], a3 = src[3];
        float4* d = (float4*)(sx + xr*XPAD + xc);
        d[0]=a0; d[1]=a1; d[2]=a2; d[3]=a3;
    }
    __syncthreads();

    const ulonglong2* sh4  = (const ulonglong2*)sh;   // row stride HPAD/4 = 65
    const ulonglong2* sWh4 = (const ulonglong2*)sWh;
    const ulonglong2* sWx4 = (const ulonglong2*)sWx;

    int whr[2], whz[2], whn[2], wxr[2], wxz[2], wxn[2];
    #pragma unroll
    for (int jj = 0; jj < 2; jj++) {
        int j = 2*tj + jj;
        whr[jj] = (0*HS + j)*(HPAD/4);
        whz[jj] = (1*HS + j)*(HPAD/4);
        whn[jj] = (2*HS + j)*(HPAD/4);
        wxr[jj] = (0*HS + j)*(XPAD/4);
        wxz[jj] = (1*HS + j)*(XPAD/4);
        wxn[jj] = (2*HS + j)*(XPAD/4);
    }

    float hnew[4][2];
    #pragma unroll
    for (int i = 0; i < 4; i++) { hnew[i][0] = 0.f; hnew[i][1] = 0.f; }

    const size_t gbase = (size_t)grp*MT*HPAD;

    for (int t = 0; t < TSTEPS; t++) {
        const int p = t & 1;

        ull ar[4][2], az[4][2], an[4][2], anh[4][2];
        #pragma unroll
        for (int i = 0; i < 4; i++)
            #pragma unroll
            for (int jj = 0; jj < 2; jj++) { ar[i][jj]=0; az[i][jj]=0; an[i][jj]=0; anh[i][jj]=0; }

        // ---- A) x-part GEMM (local; overlaps peers' STG + barrier skew) ----
        const ulonglong2* sxp = (const ulonglong2*)(sx + p*(MT*XPAD));
        #pragma unroll 2
        for (int k4 = 0; k4 < STATE_DIM/4; k4++) {
            ulonglong2 xv[4];
            #pragma unroll
            for (int i = 0; i < 4; i++) xv[i] = sxp[(tm + 16*i)*(XPAD/4) + k4];
            #pragma unroll
            for (int jj = 0; jj < 2; jj++) {
                ulonglong2 wr = sWx4[wxr[jj] + k4];
                ulonglong2 wz = sWx4[wxz[jj] + k4];
                ulonglong2 wn = sWx4[wxn[jj] + k4];
                #pragma unroll
                for (int i = 0; i < 4; i++) {
                    fma2(ar[i][jj], xv[i].x, wr.x); fma2(ar[i][jj], xv[i].y, wr.y);
                    fma2(az[i][jj], xv[i].x, wz.x); fma2(az[i][jj], xv[i].y, wz.y);
                    fma2(an[i][jj], xv[i].x, wn.x); fma2(an[i][jj], xv[i].y, wn.y);
                }
            }
        }

        // ---- B) prefetch x(t+1) into registers ----
        float4 a0, a1, a2, a3;
        const bool pf = (t+1 < TSTEPS);
        if (pf) {
            const float4* src = (const float4*)(x_seq +
                (((size_t)(grp*MT + xr))*TSTEPS + (t+1))*STATE_DIM + xc);
            a0 = src[0]; a1 = src[1]; a2 = src[2]; a3 = src[3];
        }

        // ---- C) wait (acquire) + refresh private h copy from L2 buffer ----
        if (t > 0) {
            cl_wait();
            const float4* gsrc = (const float4*)(&g_h[t & 1][gbase]);
            float4* sh4p = (float4*)sh;
            #pragma unroll
            for (int q = 0; q < 17; q++) {
                int G = q*NTHREADS + tid;               // 16B granule index
                if (G < MT*(HPAD/4)) sh4p[G] = gsrc[G]; // 1:1 padded copy
            }
        }
        __syncthreads();

        // ---- D) h-part GEMM: K=256 ----
        #pragma unroll 2
        for (int k4 = 0; k4 < HID/4; k4++) {
            ulonglong2 hv[4];
            #pragma unroll
            for (int i = 0; i < 4; i++) hv[i] = sh4[(tm + 16*i)*(HPAD/4) + k4];
            #pragma unroll
            for (int jj = 0; jj < 2; jj++) {
                ulonglong2 wr = sWh4[whr[jj] + k4];
                ulonglong2 wz = sWh4[whz[jj] + k4];
                ulonglong2 wn = sWh4[whn[jj] + k4];
                #pragma unroll
                for (int i = 0; i < 4; i++) {
                    fma2(ar[i][jj],  hv[i].x, wr.x); fma2(ar[i][jj],  hv[i].y, wr.y);
                    fma2(az[i][jj],  hv[i].x, wz.x); fma2(az[i][jj],  hv[i].y, wz.y);
                    fma2(anh[i][jj], hv[i].x, wn.x); fma2(anh[i][jj], hv[i].y, wn.y);
                }
            }
        }

        // ---- E) gates + state update (h_old from registers) + STG slice ----
        float* ghw = &g_h[(t+1) & 1][gbase];
        #pragma unroll
        for (int i = 0; i < 4; i++) {
            #pragma unroll
            for (int jj = 0; jj < 2; jj++) {
                float r = sigf(red2(ar[i][jj]) + b_r[jj]);
                float z = sigf(red2(az[i][jj]) + b_z[jj]);
                float n = tanhf_fast(red2(an[i][jj]) + b_in[jj]
                                     + r*(red2(anh[i][jj]) + b_hn[jj]));
                hnew[i][jj] = (1.f - z)*n + z*hnew[i][jj];
            }
            *(float2*)&ghw[(tm + 16*i)*HPAD + jg0] = make_float2(hnew[i][0], hnew[i][1]);
        }

        // ---- F) stage prefetched x(t+1) into the other buffer ----
        if (pf) {
            float4* d = (float4*)(sx + (p^1)*(MT*XPAD) + xr*XPAD + xc);
            d[0]=a0; d[1]=a1; d[2]=a2; d[3]=a3;
        }

        // ---- G) publish: CTA-local order, then cluster release ----
        __syncthreads();
        cl_arrive();
    }

    cl_wait();   // h(T) (written at t=TSTEPS-1 into buf 0) visible everywhere

    // ================= fused heads: rows [rank*8, rank*8+8) of this group ====
    float* hh  = sx;             // [8][HID]  (sx region free now; 8704 floats)
    float* act = sx + 8*HID;     // [8][AH]
    {
        const float* ghb = &g_h[TSTEPS & 1][gbase];
        for (int idx = tid; idx < 8*HID; idx += NTHREADS)
            hh[idx] = ghb[(rank*8 + (idx >> 8))*HPAD + (idx & 255)];
    }
    __syncthreads();

    {   // base layer: thread = unit u, all 8 rows
        const int u = tid;
        float acc[8];
        float bb = b_base[u];
        #pragma unroll
        for (int r = 0; r < 8; r++) acc[r] = bb;
        const float4* w4 = (const float4*)(w_base + (size_t)u*HID);
        #pragma unroll 4
        for (int k4 = 0; k4 < HID/4; k4++) {
            float4 w = w4[k4];
            #pragma unroll
            for (int r = 0; r < 8; r++) {
                float4 h = *(const float4*)&hh[r*HID + k4*4];
                acc[r] = fmaf(h.x, w.x, acc[r]);
                acc[r] = fmaf(h.y, w.y, acc[r]);
                acc[r] = fmaf(h.z, w.z, acc[r]);
                acc[r] = fmaf(h.w, w.w, acc[r]);
            }
        }
        #pragma unroll
        for (int r = 0; r < 8; r++) act[r*AH + u] = fmaxf(acc[r], 0.f);
    }
    __syncthreads();

    if (tid < 8*ADIM) {          // 64 threads: (row, dim) pairs
        const int r = tid >> 3, d = tid & 7;
        float sd = b_dir[d], sm = b_mag[d];
        const float* wd = w_dir + (size_t)d*AH;
        const float* wm = w_mag + (size_t)d*AH;
        #pragma unroll 8
        for (int k = 0; k < AH; k++) {
            float a = act[r*AH + k];
            sd = fmaf(a, wd[k], sd);
            sm = fmaf(a, wm[k], sm);
        }
        out[(grp*MT + rank*8 + r)*ADIM + d] = tanhf_fast(sd) * sigf(sm);
    }
}

// ---------------- launch ----------------
extern "C" void kernel_launch(void* const* d_in, const int* in_sizes, int n_in,
                              void* d_out, int out_size)
{
    (void)in_sizes; (void)n_in; (void)out_size;
    const float* x_seq  = (const float*)d_in[0];
    const float* w_ih   = (const float*)d_in[1];
    const float* w_hh   = (const float*)d_in[2];
    const float* b_ih   = (const float*)d_in[3];
    const float* b_hh   = (const float*)d_in[4];
    const float* w_base = (const float*)d_in[5];
    const float* b_base = (const float*)d_in[6];
    const float* w_dir  = (const float*)d_in[7];
    const float* b_dir  = (const float*)d_in[8];
    const float* w_mag  = (const float*)d_in[9];
    const float* b_mag  = (const float*)d_in[10];
    float* out = (float*)d_out;

    cudaFuncSetAttribute(gru_kernel, cudaFuncAttributeMaxDynamicSharedMemorySize, SMEM_BYTES);
    gru_kernel<<<GRID_SZ, NTHREADS, SMEM_BYTES>>>(
        x_seq, w_ih, w_hh, b_ih, b_hh,
        w_base, b_base, w_dir, b_dir, w_mag, b_mag, out);
}

// round 14
// speedup vs baseline: 1.2181x; 1.0014x over previous
#include <cuda_runtime.h>
#include <cstdint>

typedef unsigned long long ull;

#define STATE_DIM 64
#define HID       256
#define AH        256
#define ADIM      8
#define BATCH     1024
#define TSTEPS    512

#define CLUSTER_C 8
#define HS        32          // hidden units per CTA
#define MT        64          // batch rows per cluster group
#define NGROUP    (BATCH/MT)  // 16
#define GRID_SZ   (NGROUP*CLUSTER_C) // 128
#define NTHREADS  256

#define HPAD 260              // h/w row stride (floats); 65 float4 per row
#define XPAD 68               // x row stride (floats)

#define SMEM_FLOATS (3*HS*HPAD + 3*HS*XPAD + MT*HPAD + 2*MT*XPAD)
#define SMEM_BYTES  (SMEM_FLOATS*4)   // 227328 B

// double-buffered h exchange through L2 (padded layout, zero-initialized)
__device__ float g_h[2][NGROUP*MT*HPAD];   // 2 x 16 x 64 x 260 x 4B = 2.1 MB

// ---------------- helpers ----------------
__device__ __forceinline__ void fma2(ull &acc, ull a, ull b){
    asm("fma.rn.f32x2 %0, %1, %2, %0;" : "+l"(acc) : "l"(a), "l"(b));
}
__device__ __forceinline__ float red2(ull v){
    float x, y;
    asm("mov.b64 {%0, %1}, %2;" : "=f"(x), "=f"(y) : "l"(v));
    return x + y;
}
__device__ __forceinline__ float sigf(float x){
    return __fdividef(1.f, 1.f + __expf(-x));
}
__device__ __forceinline__ float tanhf_fast(float x){
    return 1.f - __fdividef(2.f, __expf(2.f*x) + 1.f);
}
__device__ __forceinline__ void cl_arrive(){   // release at cluster scope
    asm volatile("barrier.cluster.arrive.aligned;" ::: "memory");
}
__device__ __forceinline__ void cl_wait(){     // acquire at cluster scope
    asm volatile("barrier.cluster.wait.aligned;" ::: "memory");
}

// ---------------- fused GRU + heads ----------------
// Cluster of 8 CTAs per batch group of 64 rows. CTA rank owns hidden slice
// [rank*32, rank*32+32); W slices smem-resident. h exchanged per step through
// a double-buffered global (L2) buffer: STG own 8KB slice -> cluster barrier
// (release/acquire) -> LDG full 64KB group-h into private smem (1:1 padded
// copy: coalesced LDG, conflict-free STS). ONE cluster barrier per step.
// Per-step: x-GEMM(t) | prefetch x(t+1) | wait | copy h(t) | bar | h-GEMM |
// gates (h_old from regs) | STG h(t+1) | stage x | bar | arrive.
__global__ void __launch_bounds__(NTHREADS, 1) __cluster_dims__(CLUSTER_C, 1, 1)
gru_kernel(const float* __restrict__ x_seq, const float* __restrict__ w_ih,
           const float* __restrict__ w_hh, const float* __restrict__ b_ih,
           const float* __restrict__ b_hh,
           const float* __restrict__ w_base, const float* __restrict__ b_base,
           const float* __restrict__ w_dir,  const float* __restrict__ b_dir,
           const float* __restrict__ w_mag,  const float* __restrict__ b_mag,
           float* __restrict__ out)
{
    extern __shared__ float smem[];
    float* sWh = smem;                       // [3*HS][HPAD]
    float* sWx = sWh + 3*HS*HPAD;            // [3*HS][XPAD]
    float* sh  = sWx + 3*HS*XPAD;            // [MT][HPAD]   private copy of group h
    float* sx  = sh  + MT*HPAD;              // [2][MT][XPAD]

    const int tid  = threadIdx.x;
    const int tm   = tid & 15;               // rows tm, tm+16, tm+32, tm+48
    const int tj   = tid >> 4;               // local units 2*tj, 2*tj+1
    const int rank = blockIdx.x & (CLUSTER_C-1);
    const int grp  = blockIdx.x >> 3;
    const int jg0  = rank*HS + 2*tj;

    // --- load weight slices into smem ---
    for (int idx = tid; idx < 3*HS*HID; idx += NTHREADS) {
        int k = idx & (HID-1); int row = idx >> 8;
        sWh[row*HPAD + k] = w_hh[((row>>5)*HID + rank*HS + (row&31))*HID + k];
    }
    for (int idx = tid; idx < 3*HS*STATE_DIM; idx += NTHREADS) {
        int k = idx & (STATE_DIM-1); int row = idx >> 6;
        sWx[row*XPAD + k] = w_ih[((row>>5)*HID + rank*HS + (row&31))*STATE_DIM + k];
    }
    for (int idx = tid; idx < MT*HPAD; idx += NTHREADS) sh[idx] = 0.f;  // h(0)=0

    // --- biases ---
    float b_r[2], b_z[2], b_in[2], b_hn[2];
    #pragma unroll
    for (int jj = 0; jj < 2; jj++) {
        int jg = jg0 + jj;
        b_r[jj]  = b_ih[jg]        + b_hh[jg];
        b_z[jj]  = b_ih[HID+jg]    + b_hh[HID+jg];
        b_in[jj] = b_ih[2*HID+jg];
        b_hn[jj] = b_hh[2*HID+jg];
    }

    // --- x(t=0) into buffer 0 ---
    const int xr = tid >> 2, xc = (tid & 3) << 4;
    {
        const float4* src = (const float4*)(x_seq + ((size_t)(grp*MT + xr))*TSTEPS*STATE_DIM + xc);
        float4 a0 = src[0], a1 = src[1], a2 = src[2], a3 = src[3];
        float4* d = (float4*)(sx + xr*XPAD + xc);
        d[0]=a0; d[1]=a1; d[2]=a2; d[3]=a3;
    }
    __syncthreads();

    const ulonglong2* sh4  = (const ulonglong2*)sh;   // row stride HPAD/4 = 65
    const ulonglong2* sWh4 = (const ulonglong2*)sWh;
    const ulonglong2* sWx4 = (const ulonglong2*)sWx;

    int whr[2], whz[2], whn[2], wxr[2], wxz[2], wxn[2];
    #pragma unroll
    for (int jj = 0; jj < 2; jj++) {
        int j = 2*tj + jj;
        whr[jj] = (0*HS + j)*(HPAD/4);
        whz[jj] = (1*HS + j)*(HPAD/4);
        whn[jj] = (2*HS + j)*(HPAD/4);
        wxr[jj] = (0*HS + j)*(XPAD/4);
        wxz[jj] = (1*HS + j)*(XPAD/4);
        wxn[jj] = (2*HS + j)*(XPAD/4);
    }

    float hnew[4][2];
    #pragma unroll
    for (int i = 0; i < 4; i++) { hnew[i][0] = 0.f; hnew[i][1] = 0.f; }

    const size_t gbase = (size_t)grp*MT*HPAD;

    for (int t = 0; t < TSTEPS; t++) {
        const int p = t & 1;

        ull ar[4][2], az[4][2], an[4][2], anh[4][2];
        #pragma unroll
        for (int i = 0; i < 4; i++)
            #pragma unroll
            for (int jj = 0; jj < 2; jj++) { ar[i][jj]=0; az[i][jj]=0; an[i][jj]=0; anh[i][jj]=0; }

        // ---- A) x-part GEMM (local; overlaps peers' STG + barrier skew) ----
        const ulonglong2* sxp = (const ulonglong2*)(sx + p*(MT*XPAD));
        #pragma unroll 2
        for (int k4 = 0; k4 < STATE_DIM/4; k4++) {
            ulonglong2 xv[4];
            #pragma unroll
            for (int i = 0; i < 4; i++) xv[i] = sxp[(tm + 16*i)*(XPAD/4) + k4];
            #pragma unroll
            for (int jj = 0; jj < 2; jj++) {
                ulonglong2 wr = sWx4[wxr[jj] + k4];
                ulonglong2 wz = sWx4[wxz[jj] + k4];
                ulonglong2 wn = sWx4[wxn[jj] + k4];
                #pragma unroll
                for (int i = 0; i < 4; i++) {
                    fma2(ar[i][jj], xv[i].x, wr.x); fma2(ar[i][jj], xv[i].y, wr.y);
                    fma2(az[i][jj], xv[i].x, wz.x); fma2(az[i][jj], xv[i].y, wz.y);
                    fma2(an[i][jj], xv[i].x, wn.x); fma2(an[i][jj], xv[i].y, wn.y);
                }
            }
        }

        // ---- B) prefetch x(t+1) into registers ----
        float4 a0, a1, a2, a3;
        const bool pf = (t+1 < TSTEPS);
        if (pf) {
            const float4* src = (const float4*)(x_seq +
                (((size_t)(grp*MT + xr))*TSTEPS + (t+1))*STATE_DIM + xc);
            a0 = src[0]; a1 = src[1]; a2 = src[2]; a3 = src[3];
        }

        // ---- C) wait (acquire) + refresh private h copy from L2 buffer ----
        if (t > 0) {
            cl_wait();
            const float4* gsrc = (const float4*)(&g_h[t & 1][gbase]);
            float4* sh4p = (float4*)sh;
            #pragma unroll
            for (int q = 0; q < 17; q++) {
                int G = q*NTHREADS + tid;               // 16B granule index
                if (G < MT*(HPAD/4)) sh4p[G] = gsrc[G]; // 1:1 padded copy
            }
        }
        __syncthreads();

        // ---- D) h-part GEMM: K=256 ----
        #pragma unroll 2
        for (int k4 = 0; k4 < HID/4; k4++) {
            ulonglong2 hv[4];
            #pragma unroll
            for (int i = 0; i < 4; i++) hv[i] = sh4[(tm + 16*i)*(HPAD/4) + k4];
            #pragma unroll
            for (int jj = 0; jj < 2; jj++) {
                ulonglong2 wr = sWh4[whr[jj] + k4];
                ulonglong2 wz = sWh4[whz[jj] + k4];
                ulonglong2 wn = sWh4[whn[jj] + k4];
                #pragma unroll
                for (int i = 0; i < 4; i++) {
                    fma2(ar[i][jj],  hv[i].x, wr.x); fma2(ar[i][jj],  hv[i].y, wr.y);
                    fma2(az[i][jj],  hv[i].x, wz.x); fma2(az[i][jj],  hv[i].y, wz.y);
                    fma2(anh[i][jj], hv[i].x, wn.x); fma2(anh[i][jj], hv[i].y, wn.y);
                }
            }
        }

        // ---- E) gates + state update (h_old from registers) + STG slice ----
        float* ghw = &g_h[(t+1) & 1][gbase];
        #pragma unroll
        for (int i = 0; i < 4; i++) {
            #pragma unroll
            for (int jj = 0; jj < 2; jj++) {
                float r = sigf(red2(ar[i][jj]) + b_r[jj]);
                float z = sigf(red2(az[i][jj]) + b_z[jj]);
                float n = tanhf_fast(red2(an[i][jj]) + b_in[jj]
                                     + r*(red2(anh[i][jj]) + b_hn[jj]));
                hnew[i][jj] = (1.f - z)*n + z*hnew[i][jj];
            }
            *(float2*)&ghw[(tm + 16*i)*HPAD + jg0] = make_float2(hnew[i][0], hnew[i][1]);
        }

        // ---- F) stage prefetched x(t+1) into the other buffer ----
        if (pf) {
            float4* d = (float4*)(sx + (p^1)*(MT*XPAD) + xr*XPAD + xc);
            d[0]=a0; d[1]=a1; d[2]=a2; d[3]=a3;
        }

        // ---- G) publish: CTA-local order, then cluster release ----
        __syncthreads();
        cl_arrive();
    }

    cl_wait();   // h(T) (written at t=TSTEPS-1 into buf 0) visible everywhere

    // ================= fused heads: rows [rank*8, rank*8+8) of this group ====
    float* hh  = sx;             // [8][HID]  (sx region free now; 8704 floats)
    float* act = sx + 8*HID;     // [8][AH]
    {
        const float* ghb = &g_h[TSTEPS & 1][gbase];
        for (int idx = tid; idx < 8*HID; idx += NTHREADS)
            hh[idx] = ghb[(rank*8 + (idx >> 8))*HPAD + (idx & 255)];
    }
    __syncthreads();

    {   // base layer: thread = unit u, all 8 rows
        const int u = tid;
        float acc[8];
        float bb = b_base[u];
        #pragma unroll
        for (int r = 0; r < 8; r++) acc[r] = bb;
        const float4* w4 = (const float4*)(w_base + (size_t)u*HID);
        #pragma unroll 4
        for (int k4 = 0; k4 < HID/4; k4++) {
            float4 w = w4[k4];
            #pragma unroll
            for (int r = 0; r < 8; r++) {
                float4 h = *(const float4*)&hh[r*HID + k4*4];
                acc[r] = fmaf(h.x, w.x, acc[r]);
                acc[r] = fmaf(h.y, w.y, acc[r]);
                acc[r] = fmaf(h.z, w.z, acc[r]);
                acc[r] = fmaf(h.w, w.w, acc[r]);
            }
        }
        #pragma unroll
        for (int r = 0; r < 8; r++) act[r*AH + u] = fmaxf(acc[r], 0.f);
    }
    __syncthreads();

    if (tid < 8*ADIM) {          // 64 threads: (row, dim) pairs
        const int r = tid >> 3, d = tid & 7;
        float sd = b_dir[d], sm = b_mag[d];
        const float* wd = w_dir + (size_t)d*AH;
        const float* wm = w_mag + (size_t)d*AH;
        #pragma unroll 8
        for (int k = 0; k < AH; k++) {
            float a = act[r*AH + k];
            sd = fmaf(a, wd[k], sd);
            sm = fmaf(a, wm[k], sm);
        }
        out[(grp*MT + rank*8 + r)*ADIM + d] = tanhf_fast(sd) * sigf(sm);
    }
}

// ---------------- launch ----------------
extern "C" void kernel_launch(void* const* d_in, const int* in_sizes, int n_in,
                              void* d_out, int out_size)
{
    (void)in_sizes; (void)n_in; (void)out_size;
    const float* x_seq  = (const float*)d_in[0];
    const float* w_ih   = (const float*)d_in[1];
    const float* w_hh   = (const float*)d_in[2];
    const float* b_ih   = (const float*)d_in[3];
    const float* b_hh   = (const float*)d_in[4];
    const float* w_base = (const float*)d_in[5];
    const float* b_base = (const float*)d_in[6];
    const float* w_dir  = (const float*)d_in[7];
    const float* b_dir  = (const float*)d_in[8];
    const float* w_mag  = (const float*)d_in[9];
    const float* b_mag  = (const float*)d_in[10];
    float* out = (float*)d_out;

    cudaFuncSetAttribute(gru_kernel, cudaFuncAttributeMaxDynamicSharedMemorySize, SMEM_BYTES);
    gru_kernel<<<GRID_SZ, NTHREADS, SMEM_BYTES>>>(
        x_seq, w_ih, w_hh, b_ih, b_hh,
        w_base, b_base, w_dir, b_dir, w_mag, b_mag, out);
}

// round 16
// speedup vs baseline: 1.7972x; 1.4755x over previous
#include <cuda_runtime.h>
#include <cuda_bf16.h>
#include <cstdint>

#define STATE_DIM 64
#define HID       256
#define ADIM      8
#define BATCH     1024
#define TSTEPS    512

#define NTHREADS  256
#define GRID_SZ   128          // 16 groups x 8 CTAs (cluster)
#define MT        64           // batch rows per cluster group / per CTA tile

#define APAD   328             // A row stride in bf16 (656B; 656%128=16 -> ldmatrix conflict-free)
#define ASTR   656
#define WBSTR  656             // WB row stride bytes ([96][328] bf16)
#define WXPAD  72
#define WXSTR  144             // [32][72] bf16
#define DSTR   132             // D scratch row stride (floats)

// SMEM byte offsets
#define S_BIAS 16
#define S_WBH  1024
#define S_WBL  (S_WBH + 96*WBSTR)            // 64000
#define S_WXH  (S_WBL + 96*WBSTR)            // 126976
#define S_WXL  (S_WXH + 32*WXSTR)            // 131584
#define S_AH   (S_WXL + 32*WXSTR)            // 136192 (1024-aligned)
#define S_AL   (S_AH + MT*ASTR)              // 178176
#define SMEM_BYTES (S_AL + MT*ASTR)          // 220160

// h exchange: packed (hi | lo<<16) bf16 per element, double buffered
__device__ uint32_t g_h[2][BATCH][HID];

// ---------------- helpers ----------------
__device__ __forceinline__ uint32_t smem_u32(const void* p){
    uint32_t a;
    asm("{ .reg .u64 t; cvta.to.shared.u64 t, %1; cvt.u32.u64 %0, t; }" : "=r"(a) : "l"(p));
    return a;
}
__device__ __forceinline__ float sigf(float x){
    return __fdividef(1.f, 1.f + __expf(-x));
}
__device__ __forceinline__ float tanhf_fast(float x){
    return 1.f - __fdividef(2.f, __expf(2.f*x) + 1.f);
}
__device__ __forceinline__ void cl_arrive(){
    asm volatile("barrier.cluster.arrive.aligned;" ::: "memory");
}
__device__ __forceinline__ void cl_wait(){
    asm volatile("barrier.cluster.wait.aligned;" ::: "memory");
}
__device__ __forceinline__ void ldsm4(uint32_t r[4], uint32_t addr){
    asm volatile("ldmatrix.sync.aligned.m8n8.x4.shared.b16 {%0,%1,%2,%3}, [%4];"
        : "=r"(r[0]), "=r"(r[1]), "=r"(r[2]), "=r"(r[3]) : "r"(addr));
}
__device__ __forceinline__ void mma_bf16(float d[4], const uint32_t a[4],
                                         uint32_t b0, uint32_t b1){
    asm volatile("mma.sync.aligned.m16n8k16.row.col.f32.bf16.bf16.f32 "
        "{%0,%1,%2,%3}, {%4,%5,%6,%7}, {%8,%9}, {%0,%1,%2,%3};"
        : "+f"(d[0]), "+f"(d[1]), "+f"(d[2]), "+f"(d[3])
        : "r"(a[0]), "r"(a[1]), "r"(a[2]), "r"(a[3]), "r"(b0), "r"(b1));
}
// pack float pair -> bf16x2 hi word, bf16x2 lo word
__device__ __forceinline__ uint32_t pack_hilo(float f0, float f1, uint32_t& lo_out){
    __nv_bfloat162 hp2 = __float22bfloat162_rn(make_float2(f0, f1));
    uint32_t hp = *reinterpret_cast<uint32_t*>(&hp2);
    float g0 = f0 - __uint_as_float((hp & 0xFFFFu) << 16);
    float g1 = f1 - __uint_as_float(hp & 0xFFFF0000u);
    __nv_bfloat162 lp2 = __float22bfloat162_rn(make_float2(g0, g1));
    lo_out = *reinterpret_cast<uint32_t*>(&lp2);
    return hp;
}

// ---------------- fused GRU (mma.sync bf16 split-precision) + heads ---------
// Cluster of 8 CTAs per 64-row batch group; CTA owns 32 hidden units.
// D[64 x 128] per step: cols [0:32)=r, [32:64)=z, [64:96)=n_h, [96:128)=n_x.
// A (smem, hi/lo bf16) = [64 rows][ h(0:256) | x(256:320) ].
// B (smem, resident):  WB[96][320] = rows r|z|n_h (K-major), WX[32][64] = n_x.
// 3 mma terms: Ahi*Bhi + Alo*Bhi + Ahi*Blo (fp32 register accumulators).
__global__ void __launch_bounds__(NTHREADS, 1) __cluster_dims__(8, 1, 1)
gru_kernel(const float* __restrict__ x_seq, const float* __restrict__ w_ih,
           const float* __restrict__ w_hh, const float* __restrict__ b_ih,
           const float* __restrict__ b_hh,
           const float* __restrict__ w_base, const float* __restrict__ b_base,
           const float* __restrict__ w_dir,  const float* __restrict__ b_dir,
           const float* __restrict__ w_mag,  const float* __restrict__ b_mag,
           float* __restrict__ out)
{
    extern __shared__ __align__(1024) char smem[];
    const uint32_t sb = smem_u32(smem);
    const int tid  = threadIdx.x;
    const int wid  = tid >> 5;
    const int lane = tid & 31;
    const int rank = blockIdx.x & 7;          // unit block (32 units)
    const int grp  = blockIdx.x >> 3;         // 64-row group
    const int wm   = wid & 3;                 // m-tile (16 rows)
    const int wn   = wid >> 2;                // 0: cols 0-63 (r,z); 1: 64-127 (nh,nx)
    const int m0   = wm << 4;
    const int lgrp = lane >> 3, lr = lane & 7;

    // ---- weight tiles (hi/lo) ----
    for (int idx = tid; idx < 96*APAD; idx += NTHREADS){
        int n = idx / APAD, k = idx - n*APAD;
        int g = n >> 5, j = rank*32 + (n & 31);
        float w = 0.f;
        if (k < 256)            w = w_hh[(size_t)(g*HID + j)*HID + k];
        else if (k < 320 && g < 2) w = w_ih[(size_t)(g*HID + j)*STATE_DIM + (k - 256)];
        __nv_bfloat16 bh = __float2bfloat16(w);
        __nv_bfloat16 bl = __float2bfloat16(w - __bfloat162float(bh));
        *(__nv_bfloat16*)(smem + S_WBH + n*WBSTR + k*2) = bh;
        *(__nv_bfloat16*)(smem + S_WBL + n*WBSTR + k*2) = bl;
    }
    for (int idx = tid; idx < 32*WXPAD; idx += NTHREADS){
        int n = idx / WXPAD, k = idx - n*WXPAD;
        int j = rank*32 + n;
        float w = (k < STATE_DIM) ? w_ih[(size_t)(2*HID + j)*STATE_DIM + k] : 0.f;
        __nv_bfloat16 bh = __float2bfloat16(w);
        __nv_bfloat16 bl = __float2bfloat16(w - __bfloat162float(bh));
        *(__nv_bfloat16*)(smem + S_WXH + n*WXSTR + k*2) = bh;
        *(__nv_bfloat16*)(smem + S_WXL + n*WXSTR + k*2) = bl;
    }
    if (tid < 32){
        float* bia = (float*)(smem + S_BIAS);
        int j = rank*32 + tid;
        bia[tid]      = b_ih[j]       + b_hh[j];
        bia[32 + tid] = b_ih[HID+j]   + b_hh[HID+j];
        bia[64 + tid] = b_ih[2*HID+j];
        bia[96 + tid] = b_hh[2*HID+j];
    }
    // zero A (h(0) = 0; also clears pads)
    {
        uint4 z = make_uint4(0,0,0,0);
        uint4* a = (uint4*)(smem + S_AH);
        for (int i = tid; i < (2*MT*ASTR)/16; i += NTHREADS) a[i] = z;
    }

    // per-thread roles for staging / gates
    const int srow = tid >> 2;                 // 0..63
    const int s4   = tid & 3;
    const int rowg = grp*MT + srow;            // global batch row

    // x(0) prefetch
    float xf[16];
    {
        const float4* xs = (const float4*)(x_seq + ((size_t)rowg*TSTEPS)*STATE_DIM + s4*16);
        #pragma unroll
        for (int q = 0; q < 4; q++) ((float4*)xf)[q] = xs[q];
    }

    float hold[8];
    #pragma unroll
    for (int i = 0; i < 8; i++) hold[i] = 0.f;

    // ldmatrix per-thread offsets
    const uint32_t aoff = (uint32_t)(m0 + (lgrp & 1)*8 + lr)*ASTR + (uint32_t)(lgrp >> 1)*16;
    const uint32_t boff = (uint32_t)((lgrp >> 1)*8 + lr)*WBSTR + (uint32_t)(lgrp & 1)*16;
    const uint32_t bxof = (uint32_t)((lgrp >> 1)*8 + lr)*WXSTR + (uint32_t)(lgrp & 1)*16;

    float* Dbuf = (float*)(smem + S_AH);       // aliases A (safe: phase-separated)
    const float* bia = (const float*)(smem + S_BIAS);

    __syncthreads();
    cl_arrive();                               // publish init

    for (int t = 0; t < TSTEPS; t++){
        cl_wait();                             // h(t) exchange visible

        // ---- stage A: h from g_h (t>0), x from prefetch regs ----
        if (t > 0){
            const int kc = s4*64;
            const uint4* gsrc = (const uint4*)(&g_h[t & 1][rowg][kc]);
            char* ah = smem + S_AH + srow*ASTR + kc*2;
            char* al = smem + S_AL + srow*ASTR + kc*2;
            #pragma unroll
            for (int q = 0; q < 16; q++){
                uint4 u = gsrc[q];
                uint32_t h0 = __byte_perm(u.x, u.y, 0x5410);
                uint32_t l0 = __byte_perm(u.x, u.y, 0x7632);
                uint32_t h1 = __byte_perm(u.z, u.w, 0x5410);
                uint32_t l1 = __byte_perm(u.z, u.w, 0x7632);
                *(uint2*)(ah + q*8) = make_uint2(h0, h1);
                *(uint2*)(al + q*8) = make_uint2(l0, l1);
            }
        }
        {
            const int xk = s4*16;
            char* ah = smem + S_AH + srow*ASTR + (256 + xk)*2;
            char* al = smem + S_AL + srow*ASTR + (256 + xk)*2;
            #pragma unroll
            for (int q = 0; q < 4; q++){
                uint32_t lo0, lo1;
                uint32_t hi0 = pack_hilo(xf[q*4+0], xf[q*4+1], lo0);
                uint32_t hi1 = pack_hilo(xf[q*4+2], xf[q*4+3], lo1);
                *(uint2*)(ah + q*8) = make_uint2(hi0, hi1);
                *(uint2*)(al + q*8) = make_uint2(lo0, lo1);
            }
        }
        // prefetch x(t+1) (overlaps mma)
        if (t + 1 < TSTEPS){
            const float4* xs = (const float4*)(x_seq +
                ((size_t)rowg*TSTEPS + (t+1))*STATE_DIM + s4*16);
            #pragma unroll
            for (int q = 0; q < 4; q++) ((float4*)xf)[q] = xs[q];
        }
        __syncthreads();

        // ---- mma: D[16m x 64n] per warp, 3 split-precision terms ----
        float d[8][4];
        #pragma unroll
        for (int n = 0; n < 8; n++){ d[n][0]=0.f; d[n][1]=0.f; d[n][2]=0.f; d[n][3]=0.f; }

        if (wn == 0){
            // r,z: WB rows 0-63, K = 320 (20 k-tiles)
            #pragma unroll 4
            for (int kt = 0; kt < 20; kt++){
                uint32_t ah[4], al[4];
                ldsm4(ah, sb + S_AH + aoff + kt*32);
                ldsm4(al, sb + S_AL + aoff + kt*32);
                #pragma unroll
                for (int n4 = 0; n4 < 4; n4++){
                    uint32_t bw = (uint32_t)(n4*16)*WBSTR + boff + kt*32;
                    uint32_t bh[4], bl[4];
                    ldsm4(bh, sb + S_WBH + bw);
                    mma_bf16(d[n4*2],   ah, bh[0], bh[1]);
                    mma_bf16(d[n4*2+1], ah, bh[2], bh[3]);
                    mma_bf16(d[n4*2],   al, bh[0], bh[1]);
                    mma_bf16(d[n4*2+1], al, bh[2], bh[3]);
                    ldsm4(bl, sb + S_WBL + bw);
                    mma_bf16(d[n4*2],   ah, bl[0], bl[1]);
                    mma_bf16(d[n4*2+1], ah, bl[2], bl[3]);
                }
            }
        } else {
            // n_h: WB rows 64-95, K = 256 (16 k-tiles) -> d[0..3]
            #pragma unroll 4
            for (int kt = 0; kt < 16; kt++){
                uint32_t ah[4], al[4];
                ldsm4(ah, sb + S_AH + aoff + kt*32);
                ldsm4(al, sb + S_AL + aoff + kt*32);
                #pragma unroll
                for (int n4 = 0; n4 < 2; n4++){
                    uint32_t bw = (uint32_t)(64 + n4*16)*WBSTR + boff + kt*32;
                    uint32_t bh[4], bl[4];
                    ldsm4(bh, sb + S_WBH + bw);
                    mma_bf16(d[n4*2],   ah, bh[0], bh[1]);
                    mma_bf16(d[n4*2+1], ah, bh[2], bh[3]);
                    mma_bf16(d[n4*2],   al, bh[0], bh[1]);
                    mma_bf16(d[n4*2+1], al, bh[2], bh[3]);
                    ldsm4(bl, sb + S_WBL + bw);
                    mma_bf16(d[n4*2],   ah, bl[0], bl[1]);
                    mma_bf16(d[n4*2+1], ah, bl[2], bl[3]);
                }
            }
            // n_x: WX rows 0-31, A k-tiles 16-19 -> d[4..7]
            #pragma unroll
            for (int kt = 0; kt < 4; kt++){
                uint32_t ah[4], al[4];
                ldsm4(ah, sb + S_AH + aoff + (16 + kt)*32);
                ldsm4(al, sb + S_AL + aoff + (16 + kt)*32);
                #pragma unroll
                for (int n4 = 0; n4 < 2; n4++){
                    uint32_t bw = (uint32_t)(n4*16)*WXSTR + bxof + kt*32;
                    uint32_t bh[4], bl[4];
                    ldsm4(bh, sb + S_WXH + bw);
                    mma_bf16(d[4+n4*2],   ah, bh[0], bh[1]);
                    mma_bf16(d[4+n4*2+1], ah, bh[2], bh[3]);
                    mma_bf16(d[4+n4*2],   al, bh[0], bh[1]);
                    mma_bf16(d[4+n4*2+1], al, bh[2], bh[3]);
                    ldsm4(bl, sb + S_WXL + bw);
                    mma_bf16(d[4+n4*2],   ah, bl[0], bl[1]);
                    mma_bf16(d[4+n4*2+1], ah, bl[2], bl[3]);
                }
            }
        }
        __syncthreads();   // all ldmatrix reads of A done -> Dbuf may overwrite

        // ---- write D fragments to scratch ----
        {
            const int r0 = m0 + (lane >> 2);
            const int c0 = wn*64 + (lane & 3)*2;
            #pragma unroll
            for (int n = 0; n < 8; n++){
                int c = c0 + n*8;
                *(float2*)&Dbuf[r0*DSTR + c]       = make_float2(d[n][0], d[n][1]);
                *(float2*)&Dbuf[(r0+8)*DSTR + c]   = make_float2(d[n][2], d[n][3]);
            }
        }
        __syncthreads();

        // ---- gates + state update + exchange STG ----
        {
            const int uu = s4*8;
            const float* Dr = &Dbuf[srow*DSTR];
            uint32_t hw[8];
            #pragma unroll
            for (int q = 0; q < 2; q++){
                float4 vr = *(const float4*)&Dr[uu + q*4];
                float4 vz = *(const float4*)&Dr[32 + uu + q*4];
                float4 vh = *(const float4*)&Dr[64 + uu + q*4];
                float4 vx = *(const float4*)&Dr[96 + uu + q*4];
                const float* fr = &vr.x; const float* fz = &vz.x;
                const float* fh = &vh.x; const float* fx = &vx.x;
                #pragma unroll
                for (int i = 0; i < 4; i++){
                    int u = uu + q*4 + i;
                    float r = sigf(fr[i] + bia[u]);
                    float z = sigf(fz[i] + bia[32+u]);
                    float n = tanhf_fast(fx[i] + bia[64+u] + r*(fh[i] + bia[96+u]));
                    float h = (1.f - z)*n + z*hold[q*4+i];
                    hold[q*4+i] = h;
                    __nv_bfloat16 bh = __float2bfloat16(h);
                    uint16_t us = __bfloat16_as_ushort(bh);
                    float fhh = __uint_as_float((uint32_t)us << 16);
                    __nv_bfloat16 bl = __float2bfloat16(h - fhh);
                    hw[q*4+i] = (uint32_t)us | ((uint32_t)__bfloat16_as_ushort(bl) << 16);
                }
            }
            uint4* gdst = (uint4*)(&g_h[(t+1) & 1][rowg][rank*32 + uu]);
            gdst[0] = make_uint4(hw[0], hw[1], hw[2], hw[3]);
            gdst[1] = make_uint4(hw[4], hw[5], hw[6], hw[7]);
        }
        __syncthreads();
        cl_arrive();                           // publish h(t+1)
    }

    cl_wait();                                 // h(T) in g_h[0] visible

    // ================= fused heads: 8 rows per CTA ===========================
    {
        float* hh  = (float*)(smem + S_AH);            // [8][256]
        float* act = hh + 8*HID;                        // [8][256]
        const int hb = rank*8;
        for (int idx = tid; idx < 8*HID; idx += NTHREADS){
            uint32_t w = g_h[0][grp*MT + hb + (idx >> 8)][idx & 255];
            hh[idx] = __uint_as_float((w & 0xFFFFu) << 16)
                    + __uint_as_float(w & 0xFFFF0000u);
        }
        __syncthreads();

        {   // base layer: thread = unit u, all 8 rows
            const int u = tid;
            float acc[8];
            float bb = b_base[u];
            #pragma unroll
            for (int r = 0; r < 8; r++) acc[r] = bb;
            const float4* wv = (const float4*)(w_base + (size_t)u*HID);
            #pragma unroll 4
            for (int k4 = 0; k4 < HID/4; k4++){
                float4 w = wv[k4];
                #pragma unroll
                for (int r = 0; r < 8; r++){
                    float4 h = *(const float4*)&hh[r*HID + k4*4];
                    acc[r] = fmaf(h.x, w.x, acc[r]);
                    acc[r] = fmaf(h.y, w.y, acc[r]);
                    acc[r] = fmaf(h.z, w.z, acc[r]);
                    acc[r] = fmaf(h.w, w.w, acc[r]);
                }
            }
            #pragma unroll
            for (int r = 0; r < 8; r++) act[r*HID + u] = fmaxf(acc[r], 0.f);
        }
        __syncthreads();

        if (tid < 8*ADIM){
            const int r = tid >> 3, dd = tid & 7;
            float sd = b_dir[dd], sm = b_mag[dd];
            const float* wd = w_dir + (size_t)dd*HID;
            const float* wm = w_mag + (size_t)dd*HID;
            #pragma unroll 8
            for (int k = 0; k < HID; k++){
                float a = act[r*HID + k];
                sd = fmaf(a, wd[k], sd);
                sm = fmaf(a, wm[k], sm);
            }
            out[(grp*MT + hb + r)*ADIM + dd] = tanhf_fast(sd) * sigf(sm);
        }
    }
}

// ---------------- launch ----------------
extern "C" void kernel_launch(void* const* d_in, const int* in_sizes, int n_in,
                              void* d_out, int out_size)
{
    (void)in_sizes; (void)n_in; (void)out_size;
    const float* x_seq  = (const float*)d_in[0];
    const float* w_ih   = (const float*)d_in[1];
    const float* w_hh   = (const float*)d_in[2];
    const float* b_ih   = (const float*)d_in[3];
    const float* b_hh   = (const float*)d_in[4];
    const float* w_base = (const float*)d_in[5];
    const float* b_base = (const float*)d_in[6];
    const float* w_dir  = (const float*)d_in[7];
    const float* b_dir  = (const float*)d_in[8];
    const float* w_mag  = (const float*)d_in[9];
    const float* b_mag  = (const float*)d_in[10];
    float* out = (float*)d_out;

    cudaFuncSetAttribute(gru_kernel, cudaFuncAttributeMaxDynamicSharedMemorySize, SMEM_BYTES);
    gru_kernel<<<GRID_SZ, NTHREADS, SMEM_BYTES>>>(
        x_seq, w_ih, w_hh, b_ih, b_hh,
        w_base, b_base, w_dir, b_dir, w_mag, b_mag, out);
}

// round 17
// speedup vs baseline: 2.6394x; 1.4686x over previous
#include <cuda_runtime.h>
#include <cuda_bf16.h>
#include <cstdint>

#define STATE_DIM 64
#define HID       256
#define ADIM      8
#define BATCH     1024
#define TSTEPS    512

#define NTHREADS  512
#define GRID_SZ   128          // 16 groups x 8 CTAs (cluster)
#define MT        64           // batch rows per cluster group / per CTA tile

#define APAD   328             // A row stride in bf16
#define ASTR   656
#define WBSTR  656             // WB row stride bytes ([96][328] bf16)
#define WXPAD  72
#define WXSTR  144             // [32][72] bf16
#define DSTR   132             // D scratch row stride (floats)

// SMEM byte offsets
#define S_BIAS 16
#define S_WBH  1024
#define S_WBL  (S_WBH + 96*WBSTR)
#define S_WXH  (S_WBL + 96*WBSTR)
#define S_WXL  (S_WXH + 32*WXSTR)
#define S_AH   (S_WXL + 32*WXSTR)
#define S_AL   (S_AH + MT*ASTR)
#define SMEM_BYTES (S_AL + MT*ASTR)   // 220160

// h exchange: packed (hi | lo<<16) bf16 per element, double buffered
__device__ uint32_t g_h[2][BATCH][HID];

// ---------------- helpers ----------------
__device__ __forceinline__ uint32_t smem_u32(const void* p){
    uint32_t a;
    asm("{ .reg .u64 t; cvta.to.shared.u64 t, %1; cvt.u32.u64 %0, t; }" : "=r"(a) : "l"(p));
    return a;
}
__device__ __forceinline__ float sigf(float x){
    return __fdividef(1.f, 1.f + __expf(-x));
}
__device__ __forceinline__ float tanhf_fast(float x){
    return 1.f - __fdividef(2.f, __expf(2.f*x) + 1.f);
}
__device__ __forceinline__ void cl_arrive(){
    asm volatile("barrier.cluster.arrive.aligned;" ::: "memory");
}
__device__ __forceinline__ void cl_wait(){
    asm volatile("barrier.cluster.wait.aligned;" ::: "memory");
}
__device__ __forceinline__ void ldsm4(uint32_t r[4], uint32_t addr){
    asm volatile("ldmatrix.sync.aligned.m8n8.x4.shared.b16 {%0,%1,%2,%3}, [%4];"
        : "=r"(r[0]), "=r"(r[1]), "=r"(r[2]), "=r"(r[3]) : "r"(addr));
}
__device__ __forceinline__ void mma_bf16(float d[4], const uint32_t a[4],
                                         uint32_t b0, uint32_t b1){
    asm volatile("mma.sync.aligned.m16n8k16.row.col.f32.bf16.bf16.f32 "
        "{%0,%1,%2,%3}, {%4,%5,%6,%7}, {%8,%9}, {%0,%1,%2,%3};"
        : "+f"(d[0]), "+f"(d[1]), "+f"(d[2]), "+f"(d[3])
        : "r"(a[0]), "r"(a[1]), "r"(a[2]), "r"(a[3]), "r"(b0), "r"(b1));
}
__device__ __forceinline__ uint32_t pack_hilo(float f0, float f1, uint32_t& lo_out){
    __nv_bfloat162 hp2 = __float22bfloat162_rn(make_float2(f0, f1));
    uint32_t hp = *reinterpret_cast<uint32_t*>(&hp2);
    float g0 = f0 - __uint_as_float((hp & 0xFFFFu) << 16);
    float g1 = f1 - __uint_as_float(hp & 0xFFFF0000u);
    __nv_bfloat162 lp2 = __float22bfloat162_rn(make_float2(g0, g1));
    lo_out = *reinterpret_cast<uint32_t*>(&lp2);
    return hp;
}

// ---------------- fused GRU (mma.sync bf16 split-precision) + heads ---------
// Cluster of 8 CTAs per 64-row batch group; CTA owns 32 hidden units.
// 16 warps = 4m x 4n; wn -> gate: 0=r (K=320), 1=z (K=320), 2=nh (K=256),
// 3=nx (K=64). D[64 x 128] cols [0:32)=r [32:64)=z [64:96)=nh [96:128)=nx.
__global__ void __launch_bounds__(NTHREADS, 1) __cluster_dims__(8, 1, 1)
gru_kernel(const float* __restrict__ x_seq, const float* __restrict__ w_ih,
           const float* __restrict__ w_hh, const float* __restrict__ b_ih,
           const float* __restrict__ b_hh,
           const float* __restrict__ w_base, const float* __restrict__ b_base,
           const float* __restrict__ w_dir,  const float* __restrict__ b_dir,
           const float* __restrict__ w_mag,  const float* __restrict__ b_mag,
           float* __restrict__ out)
{
    extern __shared__ __align__(1024) char smem[];
    const uint32_t sb = smem_u32(smem);
    const int tid  = threadIdx.x;
    const int wid  = tid >> 5;
    const int lane = tid & 31;
    const int rank = blockIdx.x & 7;          // unit block (32 units)
    const int grp  = blockIdx.x >> 3;         // 64-row group
    const int wm   = wid & 3;                 // m-tile (16 rows)
    const int wn   = wid >> 2;                // gate: 0=r 1=z 2=nh 3=nx
    const int m0   = wm << 4;
    const int lgrp = lane >> 3, lr = lane & 7;

    // ---- weight tiles (hi/lo) ----
    for (int idx = tid; idx < 96*APAD; idx += NTHREADS){
        int n = idx / APAD, k = idx - n*APAD;
        int g = n >> 5, j = rank*32 + (n & 31);
        float w = 0.f;
        if (k < 256)               w = w_hh[(size_t)(g*HID + j)*HID + k];
        else if (k < 320 && g < 2) w = w_ih[(size_t)(g*HID + j)*STATE_DIM + (k - 256)];
        __nv_bfloat16 bh = __float2bfloat16(w);
        __nv_bfloat16 bl = __float2bfloat16(w - __bfloat162float(bh));
        *(__nv_bfloat16*)(smem + S_WBH + n*WBSTR + k*2) = bh;
        *(__nv_bfloat16*)(smem + S_WBL + n*WBSTR + k*2) = bl;
    }
    for (int idx = tid; idx < 32*WXPAD; idx += NTHREADS){
        int n = idx / WXPAD, k = idx - n*WXPAD;
        int j = rank*32 + n;
        float w = (k < STATE_DIM) ? w_ih[(size_t)(2*HID + j)*STATE_DIM + k] : 0.f;
        __nv_bfloat16 bh = __float2bfloat16(w);
        __nv_bfloat16 bl = __float2bfloat16(w - __bfloat162float(bh));
        *(__nv_bfloat16*)(smem + S_WXH + n*WXSTR + k*2) = bh;
        *(__nv_bfloat16*)(smem + S_WXL + n*WXSTR + k*2) = bl;
    }
    if (tid < 32){
        float* bia = (float*)(smem + S_BIAS);
        int j = rank*32 + tid;
        bia[tid]      = b_ih[j]       + b_hh[j];
        bia[32 + tid] = b_ih[HID+j]   + b_hh[HID+j];
        bia[64 + tid] = b_ih[2*HID+j];
        bia[96 + tid] = b_hh[2*HID+j];
    }
    // zero A (h(0) = 0; also clears pads)
    {
        uint4 z = make_uint4(0,0,0,0);
        uint4* a = (uint4*)(smem + S_AH);
        for (int i = tid; i < (2*MT*ASTR)/16; i += NTHREADS) a[i] = z;
    }

    // staging / gate thread roles: 8 threads per row
    const int srow = tid >> 3;                 // 0..63
    const int s8   = tid & 7;
    const int rowg = grp*MT + srow;            // global batch row

    // x(0) prefetch: 8 floats per thread
    float xf[8];
    {
        const float4* xs = (const float4*)(x_seq + ((size_t)rowg*TSTEPS)*STATE_DIM + s8*8);
        ((float4*)xf)[0] = xs[0]; ((float4*)xf)[1] = xs[1];
    }

    float hold[4];
    #pragma unroll
    for (int i = 0; i < 4; i++) hold[i] = 0.f;

    // ldmatrix per-thread offsets (same fragment patterns as R16)
    const uint32_t aoff = (uint32_t)(m0 + (lgrp & 1)*8 + lr)*ASTR + (uint32_t)(lgrp >> 1)*16;
    const uint32_t boff = (uint32_t)((lgrp >> 1)*8 + lr)*WBSTR + (uint32_t)(lgrp & 1)*16;
    const uint32_t bxof = (uint32_t)((lgrp >> 1)*8 + lr)*WXSTR + (uint32_t)(lgrp & 1)*16;

    float* Dbuf = (float*)(smem + S_AH);       // aliases A (phase-separated)
    const float* bia = (const float*)(smem + S_BIAS);

    __syncthreads();
    cl_arrive();                               // publish init

    for (int t = 0; t < TSTEPS; t++){
        cl_wait();                             // h(t) exchange visible

        // ---- A) issue all h LDGs up front (MLP = 8) ----
        uint4 hu[8];
        if (t > 0){
            const uint4* gsrc = (const uint4*)(&g_h[t & 1][rowg][0]);
            #pragma unroll
            for (int q = 0; q < 8; q++) hu[q] = gsrc[s8 + q*8];   // elems (s8 + 8q)*4
        }

        // ---- B) stage x(t) from regs (overlaps h LDG latency) ----
        {
            char* ah = smem + S_AH + srow*ASTR + (256 + s8*8)*2;
            char* al = smem + S_AL + srow*ASTR + (256 + s8*8)*2;
            uint32_t hi[4], lo[4];
            #pragma unroll
            for (int q = 0; q < 4; q++) hi[q] = pack_hilo(xf[2*q], xf[2*q+1], lo[q]);
            *(uint4*)ah = make_uint4(hi[0], hi[1], hi[2], hi[3]);
            *(uint4*)al = make_uint4(lo[0], lo[1], lo[2], lo[3]);
        }

        // ---- C) unpack h -> A smem (bank-spread: elem base (s8 + 8q)*4) ----
        if (t > 0){
            char* ah = smem + S_AH + srow*ASTR;
            char* al = smem + S_AL + srow*ASTR;
            #pragma unroll
            for (int q = 0; q < 8; q++){
                uint4 u = hu[q];
                uint32_t h0 = __byte_perm(u.x, u.y, 0x5410);
                uint32_t l0 = __byte_perm(u.x, u.y, 0x7632);
                uint32_t h1 = __byte_perm(u.z, u.w, 0x5410);
                uint32_t l1 = __byte_perm(u.z, u.w, 0x7632);
                int e2 = (s8 + q*8)*8;                  // byte offset = elem*2
                *(uint2*)(ah + e2) = make_uint2(h0, h1);
                *(uint2*)(al + e2) = make_uint2(l0, l1);
            }
        }

        // ---- D) prefetch x(t+1) ----
        if (t + 1 < TSTEPS){
            const float4* xs = (const float4*)(x_seq +
                ((size_t)rowg*TSTEPS + (t+1))*STATE_DIM + s8*8);
            float4 a0 = xs[0], a1 = xs[1];
            ((float4*)xf)[0] = a0; ((float4*)xf)[1] = a1;
        }
        __syncthreads();

        // ---- E) mma: warp = 16 rows x 32 cols of one gate ----
        float d[4][4];
        #pragma unroll
        for (int n = 0; n < 4; n++){ d[n][0]=0.f; d[n][1]=0.f; d[n][2]=0.f; d[n][3]=0.f; }

        if (wn < 2){
            const int rbase = wn*32;           // r or z rows, K = 320
            #pragma unroll 4
            for (int kt = 0; kt < 20; kt++){
                uint32_t ah[4], al[4];
                ldsm4(ah, sb + S_AH + aoff + kt*32);
                ldsm4(al, sb + S_AL + aoff + kt*32);
                #pragma unroll
                for (int n4 = 0; n4 < 2; n4++){
                    uint32_t bw = (uint32_t)(rbase + n4*16)*WBSTR + boff + kt*32;
                    uint32_t bh[4], bl[4];
                    ldsm4(bh, sb + S_WBH + bw);
                    mma_bf16(d[n4*2],   ah, bh[0], bh[1]);
                    mma_bf16(d[n4*2+1], ah, bh[2], bh[3]);
                    mma_bf16(d[n4*2],   al, bh[0], bh[1]);
                    mma_bf16(d[n4*2+1], al, bh[2], bh[3]);
                    ldsm4(bl, sb + S_WBL + bw);
                    mma_bf16(d[n4*2],   ah, bl[0], bl[1]);
                    mma_bf16(d[n4*2+1], ah, bl[2], bl[3]);
                }
            }
        } else if (wn == 2){
            #pragma unroll 4
            for (int kt = 0; kt < 16; kt++){   // nh rows 64-95, K = 256
                uint32_t ah[4], al[4];
                ldsm4(ah, sb + S_AH + aoff + kt*32);
                ldsm4(al, sb + S_AL + aoff + kt*32);
                #pragma unroll
                for (int n4 = 0; n4 < 2; n4++){
                    uint32_t bw = (uint32_t)(64 + n4*16)*WBSTR + boff + kt*32;
                    uint32_t bh[4], bl[4];
                    ldsm4(bh, sb + S_WBH + bw);
                    mma_bf16(d[n4*2],   ah, bh[0], bh[1]);
                    mma_bf16(d[n4*2+1], ah, bh[2], bh[3]);
                    mma_bf16(d[n4*2],   al, bh[0], bh[1]);
                    mma_bf16(d[n4*2+1], al, bh[2], bh[3]);
                    ldsm4(bl, sb + S_WBL + bw);
                    mma_bf16(d[n4*2],   ah, bl[0], bl[1]);
                    mma_bf16(d[n4*2+1], ah, bl[2], bl[3]);
                }
            }
        } else {
            #pragma unroll
            for (int kt = 0; kt < 4; kt++){    // nx: WX rows, A k-tiles 16-19
                uint32_t ah[4], al[4];
                ldsm4(ah, sb + S_AH + aoff + (16 + kt)*32);
                ldsm4(al, sb + S_AL + aoff + (16 + kt)*32);
                #pragma unroll
                for (int n4 = 0; n4 < 2; n4++){
                    uint32_t bw = (uint32_t)(n4*16)*WXSTR + bxof + kt*32;
                    uint32_t bh[4], bl[4];
                    ldsm4(bh, sb + S_WXH + bw);
                    mma_bf16(d[n4*2],   ah, bh[0], bh[1]);
                    mma_bf16(d[n4*2+1], ah, bh[2], bh[3]);
                    mma_bf16(d[n4*2],   al, bh[0], bh[1]);
                    mma_bf16(d[n4*2+1], al, bh[2], bh[3]);
                    ldsm4(bl, sb + S_WXL + bw);
                    mma_bf16(d[n4*2],   ah, bl[0], bl[1]);
                    mma_bf16(d[n4*2+1], ah, bl[2], bl[3]);
                }
            }
        }
        __syncthreads();   // A reads done -> Dbuf may overwrite

        // ---- F) write D fragments (warp's gate = cols wn*32..+32) ----
        {
            const int r0 = m0 + (lane >> 2);
            const int c0 = wn*32 + (lane & 3)*2;
            #pragma unroll
            for (int n = 0; n < 4; n++){
                int c = c0 + n*8;
                *(float2*)&Dbuf[r0*DSTR + c]     = make_float2(d[n][0], d[n][1]);
                *(float2*)&Dbuf[(r0+8)*DSTR + c] = make_float2(d[n][2], d[n][3]);
            }
        }
        __syncthreads();

        // ---- G) gates + state update + exchange STG (4 units/thread) ----
        {
            const int uu = s8*4;
            const float* Dr = &Dbuf[srow*DSTR];
            float4 vr = *(const float4*)&Dr[uu];
            float4 vz = *(const float4*)&Dr[32 + uu];
            float4 vh = *(const float4*)&Dr[64 + uu];
            float4 vx = *(const float4*)&Dr[96 + uu];
            float4 br = *(const float4*)&bia[uu];
            float4 bz = *(const float4*)&bia[32 + uu];
            float4 bn = *(const float4*)&bia[64 + uu];
            float4 bh2 = *(const float4*)&bia[96 + uu];
            const float* fr = &vr.x; const float* fz = &vz.x;
            const float* fh = &vh.x; const float* fx = &vx.x;
            const float* pbr = &br.x; const float* pbz = &bz.x;
            const float* pbn = &bn.x; const float* pbh = &bh2.x;
            uint32_t hw[4];
            #pragma unroll
            for (int i = 0; i < 4; i++){
                float r = sigf(fr[i] + pbr[i]);
                float z = sigf(fz[i] + pbz[i]);
                float n = tanhf_fast(fx[i] + pbn[i] + r*(fh[i] + pbh[i]));
                float h = (1.f - z)*n + z*hold[i];
                hold[i] = h;
                __nv_bfloat16 bhh = __float2bfloat16(h);
                uint16_t us = __bfloat16_as_ushort(bhh);
                float fhh = __uint_as_float((uint32_t)us << 16);
                __nv_bfloat16 bll = __float2bfloat16(h - fhh);
                hw[i] = (uint32_t)us | ((uint32_t)__bfloat16_as_ushort(bll) << 16);
            }
            *(uint4*)(&g_h[(t+1) & 1][rowg][rank*32 + uu]) =
                make_uint4(hw[0], hw[1], hw[2], hw[3]);
        }
        cl_arrive();                           // publish h(t+1)
    }

    cl_wait();                                 // h(T) in g_h[0] visible

    // ================= fused heads: 8 rows per CTA ===========================
    {
        float* hh  = (float*)(smem + S_AH);            // [8][256]
        float* act = hh + 8*HID;                        // [8][256]
        const int hb = rank*8;
        for (int idx = tid; idx < 8*HID; idx += NTHREADS){
            uint32_t w = g_h[0][grp*MT + hb + (idx >> 8)][idx & 255];
            hh[idx] = __uint_as_float((w & 0xFFFFu) << 16)
                    + __uint_as_float(w & 0xFFFF0000u);
        }
        __syncthreads();

        if (tid < 256){  // base layer: thread = unit u, all 8 rows
            const int u = tid;
            float acc[8];
            float bb = b_base[u];
            #pragma unroll
            for (int r = 0; r < 8; r++) acc[r] = bb;
            const float4* wv = (const float4*)(w_base + (size_t)u*HID);
            #pragma unroll 4
            for (int k4 = 0; k4 < HID/4; k4++){
                float4 w = wv[k4];
                #pragma unroll
                for (int r = 0; r < 8; r++){
                    float4 h = *(const float4*)&hh[r*HID + k4*4];
                    acc[r] = fmaf(h.x, w.x, acc[r]);
                    acc[r] = fmaf(h.y, w.y, acc[r]);
                    acc[r] = fmaf(h.z, w.z, acc[r]);
                    acc[r] = fmaf(h.w, w.w, acc[r]);
                }
            }
            #pragma unroll
            for (int r = 0; r < 8; r++) act[r*HID + u] = fmaxf(acc[r], 0.f);
        }
        __syncthreads();

        if (tid < 8*ADIM){
            const int r = tid >> 3, dd = tid & 7;
            float sd = b_dir[dd], sm = b_mag[dd];
            const float* wd = w_dir + (size_t)dd*HID;
            const float* wm = w_mag + (size_t)dd*HID;
            #pragma unroll 8
            for (int k = 0; k < HID; k++){
                float a = act[r*HID + k];
                sd = fmaf(a, wd[k], sd);
                sm = fmaf(a, wm[k], sm);
            }
            out[(grp*MT + hb + r)*ADIM + dd] = tanhf_fast(sd) * sigf(sm);
        }
    }
}

// ---------------- launch ----------------
extern "C" void kernel_launch(void* const* d_in, const int* in_sizes, int n_in,
                              void* d_out, int out_size)
{
    (void)in_sizes; (void)n_in; (void)out_size;
    const float* x_seq  = (const float*)d_in[0];
    const float* w_ih   = (const float*)d_in[1];
    const float* w_hh   = (const float*)d_in[2];
    const float* b_ih   = (const float*)d_in[3];
    const float* b_hh   = (const float*)d_in[4];
    const float* w_base = (const float*)d_in[5];
    const float* b_base = (const float*)d_in[6];
    const float* w_dir  = (const float*)d_in[7];
    const float* b_dir  = (const float*)d_in[8];
    const float* w_mag  = (const float*)d_in[9];
    const float* b_mag  = (const float*)d_in[10];
    float* out = (float*)d_out;

    cudaFuncSetAttribute(gru_kernel, cudaFuncAttributeMaxDynamicSharedMemorySize, SMEM_BYTES);
    gru_kernel<<<GRID_SZ, NTHREADS, SMEM_BYTES>>>(
        x_seq, w_ih, w_hh, b_ih, b_hh,
        w_base, b_base, w_dir, b_dir, w_mag, b_mag, out);
}